// round 17
// baseline (speedup 1.0000x reference)
#include <cuda_runtime.h>
#include <cuda_bf16.h>
#include <cstdint>
#include <cstddef>

// Problem constants (match reference_code)
#define NB_NODE 100000
#define FT      256
#define OUT_FT  256
#define NB_REL  4
#define BATCH   8192
#define DEG     16

// ---------------------------------------------------------------------------
// Scratch (device globals — no allocations allowed).
//   g_vh/g_vl : v_in split into bf16 hi/lo, layout [r][b][f]  (16 MB each)
//   g_wth/gwtl: W^T split into bf16 hi/lo, layout [r][n][k]   (512 KB each)
// ---------------------------------------------------------------------------
__device__ __nv_bfloat16 g_vh[(size_t)NB_REL * BATCH * FT];
__device__ __nv_bfloat16 g_vl[(size_t)NB_REL * BATCH * FT];
__device__ __nv_bfloat16 g_wth[(size_t)NB_REL * OUT_FT * FT];
__device__ __nv_bfloat16 g_wtl[(size_t)NB_REL * OUT_FT * FT];

// ---------------------------------------------------------------------------
// PTX helpers (all baseline sm_75/sm_80 PTX — no sm_103a-gated instructions)
// ---------------------------------------------------------------------------
__device__ __forceinline__ void cp16(uint32_t dst, const void* src) {
    asm volatile("cp.async.cg.shared.global [%0], [%1], 16;\n"
                 :: "r"(dst), "l"(src));
}
#define CP_COMMIT() asm volatile("cp.async.commit_group;\n" ::: "memory")
#define CP_WAIT(n)  asm volatile("cp.async.wait_group %0;\n" :: "n"(n) : "memory")

// bf16 HMMA, fp32 accumulate: D = A(16x16) * B(16x8) + D
__device__ __forceinline__ void mma16816(float* c, const uint32_t* a,
                                         const uint32_t* b) {
    asm volatile(
        "mma.sync.aligned.m16n8k16.row.col.f32.bf16.bf16.f32 "
        "{%0,%1,%2,%3}, {%4,%5,%6,%7}, {%8,%9}, {%0,%1,%2,%3};"
        : "+f"(c[0]), "+f"(c[1]), "+f"(c[2]), "+f"(c[3])
        : "r"(a[0]), "r"(a[1]), "r"(a[2]), "r"(a[3]), "r"(b[0]), "r"(b[1]));
}

// ldmatrix x4: four 8x8 b16 matrices, one per 8-lane address group
#define LDSM4(R, addr) \
    asm volatile("ldmatrix.sync.aligned.m8n8.x4.shared.b16 {%0,%1,%2,%3}, [%4];" \
                 : "=r"((R)[0]), "=r"((R)[1]), "=r"((R)[2]), "=r"((R)[3]) \
                 : "r"(addr))

// streaming (evict-first) stores to keep the feature table resident in L2
__device__ __forceinline__ void stcs_u2(void* p, uint2 v) {
    asm volatile("st.global.cs.v2.u32 [%0], {%1, %2};"
                 :: "l"(p), "r"(v.x), "r"(v.y) : "memory");
}

// ---------------------------------------------------------------------------
// Kernel 1: fused prep.
//  blocks [0, 8192): gather + mean over DEG neighbors -> bf16 hi/lo split.
//  blocks [8192, 9216): W transpose + bf16 hi/lo split.
// Gather is LTS-bound (544 MB across L2) — at its floor (~46 us).
// ---------------------------------------------------------------------------
__global__ void __launch_bounds__(256, 8)
prep_kernel(const float* __restrict__ features,
            const int* __restrict__ nidx,
            const float* __restrict__ W)
{
    if (blockIdx.x >= 8192) {
        // ---- W prep: Wt[r][n][k] = split(W[r][k][n]) ----
        const int rn = blockIdx.x - 8192;   // r*256 + n
        const int r  = rn >> 8;
        const int n  = rn & 255;
        const int k  = threadIdx.x;
        const float v = __ldg(&W[((size_t)r * FT + k) * OUT_FT + n]);
        const __nv_bfloat16 h = __float2bfloat16_rn(v);
        const __nv_bfloat16 l = __float2bfloat16_rn(v - __bfloat162float(h));
        const size_t o = (size_t)rn * FT + k;
        g_wth[o] = h;
        g_wtl[o] = l;
        return;
    }

    const int sub  = threadIdx.x >> 6;
    const int lane = threadIdx.x & 63;
    const int pair = blockIdx.x * 4 + sub;     // pair = b*NB_REL + r
    const int b    = pair >> 2;
    const int r    = pair & 3;

    const int* idx = nidx + (size_t)pair * DEG;

    float4 s = make_float4(0.f, 0.f, 0.f, 0.f);
#pragma unroll
    for (int d = 0; d < DEG; d++) {
        const int n = __ldg(&idx[d]);
        const float4 v = __ldg(((const float4*)(features + (size_t)n * FT)) + lane);
        s.x += v.x; s.y += v.y; s.z += v.z; s.w += v.w;
    }
    const float inv = 1.0f / (float)DEG;
    s.x *= inv; s.y *= inv; s.z *= inv; s.w *= inv;

    const float sv[4] = { s.x, s.y, s.z, s.w };
    union { __nv_bfloat16 b4[4]; uint2 u; } H, L;
#pragma unroll
    for (int j = 0; j < 4; j++) {
        const __nv_bfloat16 h = __float2bfloat16_rn(sv[j]);
        H.b4[j] = h;
        L.b4[j] = __float2bfloat16_rn(sv[j] - __bfloat162float(h));
    }
    const size_t o = ((size_t)(r * BATCH + b)) * FT + lane * 4;
    stcs_u2(g_vh + o, H.u);
    stcs_u2(g_vl + o, L.u);
}

// ---------------------------------------------------------------------------
// Kernel 2: mma.sync bf16 split GEMM + fused epilogue.
//   D_r = Ah*Bh + Al*Bh + Ah*Bl  (fp32 accum, 3 passes from ONE residency)
//   out  = 0.25 * sum_r prelu(D_r + bias_r)
//
// 3-stage pipeline, KC=32 chunks (32 chunks), ONE __syncthreads per chunk:
// iteration c overwrites stage (c-1)%3 which every warp finished before this
// iteration's barrier; cp.async runs 2 chunks ahead so CP_WAIT(1) is free.
// KST=40 (20-word row stride): ldmatrix rows hit banks {0,20,8,28,16,4,24,12}
// x4 words — fully disjoint, conflict-free.
// CTA: 256 thr = 8 warps (4 m x 2 n). Tile M=128, N=64. 2 CTAs/SM.
// ---------------------------------------------------------------------------
#define TM 128
#define TN 64
#define KC 32
#define KST 40                              // padded k-stride (bf16 units)
#define NSTAGE 3
#define A_ELEMS (TM * KST)                  // 5120 bf16 = 10240 B per tile
#define B_ELEMS (TN * KST)                  // 2560 bf16 =  5120 B per tile
#define STAGE_ELEMS (2 * A_ELEMS + 2 * B_ELEMS)   // Ah,Al,Bh,Bl = 30720 B
#define SMEM_DYN (NSTAGE * STAGE_ELEMS * 2) // 92160 B
#define NCH (NB_REL * (FT / KC))            // 32 chunks

__global__ void __launch_bounds__(256, 2)
rgcn_mma_kernel(const float* __restrict__ bias,
                const float* __restrict__ prelu_a,
                float* __restrict__ out)
{
    extern __shared__ __align__(16) __nv_bfloat16 smem[];
    __shared__ float biasS[NB_REL * TN];

    const int tid  = threadIdx.x;
    const int wid  = tid >> 5;
    const int lane = tid & 31;
    const int wm   = (wid & 3) * 32;        // warp m-offset
    const int wn   = (wid >> 2) * 32;       // warp n-offset
    const int g    = lane >> 2;             // 0..7
    const int t2   = (lane & 3) * 2;        // 0,2,4,6
    const int bm0  = blockIdx.x * TM;
    const int bn0  = blockIdx.y * TN;

    for (int i = tid; i < NB_REL * TN; i += 256)
        biasS[i] = __ldg(&bias[(i >> 6) * OUT_FT + bn0 + (i & 63)]);

    const uint32_t smem_b = (uint32_t)__cvta_generic_to_shared(smem);

    // ldmatrix per-lane byte offsets within a tile (constant all kernel)
    uint32_t aOff[2], bOff[2];
#pragma unroll
    for (int mt = 0; mt < 2; mt++)
        aOff[mt] = (uint32_t)(((wm + mt * 16 + (lane & 15)) * KST +
                               ((lane >> 4) * 8)) * 2);
#pragma unroll
    for (int p = 0; p < 2; p++)
        bOff[p] = (uint32_t)(((wn + p * 16 + ((lane >> 4) << 3) + (lane & 7)) * KST +
                              (((lane >> 3) & 1) << 3)) * 2);

    // chunk c -> relation r = c/8, kc0 = (c&7)*KC. Loads Ah,Al,Bh,Bl.
    auto load_chunk = [&](int c, int stage) {
        const int r   = c >> 3;
        const int kc0 = (c & 7) * KC;
        const size_t aoff = ((size_t)(r * BATCH  + bm0)) * FT + kc0;
        const size_t boff = ((size_t)(r * OUT_FT + bn0)) * FT + kc0;
        const uint32_t stAH = smem_b + (uint32_t)(stage * STAGE_ELEMS * 2);
        const uint32_t stAL = stAH + A_ELEMS * 2;
        const uint32_t stBH = stAL + A_ELEMS * 2;
        const uint32_t stBL = stBH + B_ELEMS * 2;
        // A tiles: 128 rows x 4 x 16B -> 2 cp16/thread/tile
#pragma unroll
        for (int j = 0; j < 2; j++) {
            const int idx = j * 256 + tid;
            const int row = idx >> 2;
            const int g4  = idx & 3;
            const uint32_t d = (uint32_t)(row * (KST * 2) + g4 * 16);
            const size_t   s = aoff + (size_t)row * FT + g4 * 8;
            cp16(stAH + d, g_vh + s);
            cp16(stAL + d, g_vl + s);
        }
        // B tiles: 64 rows x 4 x 16B -> 1 cp16/thread/tile
        {
            const int row = tid >> 2;
            const int g4  = tid & 3;
            const uint32_t d = (uint32_t)(row * (KST * 2) + g4 * 16);
            const size_t   s = boff + (size_t)row * FT + g4 * 8;
            cp16(stBH + d, g_wth + s);
            cp16(stBL + d, g_wtl + s);
        }
        CP_COMMIT();
    };

    float acc[2][4][4];                     // [m-tile][n-tile][frag]
    float run[2][4][4];
#pragma unroll
    for (int mt = 0; mt < 2; mt++)
#pragma unroll
        for (int nt = 0; nt < 4; nt++)
#pragma unroll
            for (int q = 0; q < 4; q++) { acc[mt][nt][q] = 0.f; run[mt][nt][q] = 0.f; }

    const float alpha = __ldg(prelu_a);

    // prologue: 2 chunks in flight
    load_chunk(0, 0);
    load_chunk(1, 1);

#pragma unroll 1
    for (int c = 0; c < NCH; c++) {
        const int stage = c % NSTAGE;

        // chunk c ready: issued <= c+2, so <=1 group may still be pending
        if (c < NCH - 1) CP_WAIT(1); else CP_WAIT(0);
        __syncthreads();    // also: all warps finished computing chunk c-1

        // prefetch chunk c+2 into stage (c+2)%3 (overwrites chunk c-1's stage)
        if (c + 2 < NCH) load_chunk(c + 2, (c + 2) % NSTAGE);

        const uint32_t stAH = smem_b + (uint32_t)(stage * STAGE_ELEMS * 2);
        const uint32_t stAL = stAH + A_ELEMS * 2;
        const uint32_t stBH = stAL + A_ELEMS * 2;
        const uint32_t stBL = stBH + B_ELEMS * 2;

#pragma unroll
        for (int k16 = 0; k16 < KC / 16; k16++) {
            const uint32_t kB = (uint32_t)(k16 * 32);   // 16 bf16 = 32 bytes
            uint32_t aH[8], aL[8], bH[8], bL[8];
            LDSM4(aH,     stAH + aOff[0] + kB);
            LDSM4(aH + 4, stAH + aOff[1] + kB);
            LDSM4(aL,     stAL + aOff[0] + kB);
            LDSM4(aL + 4, stAL + aOff[1] + kB);
            LDSM4(bH,     stBH + bOff[0] + kB);
            LDSM4(bH + 4, stBH + bOff[1] + kB);
            LDSM4(bL,     stBL + bOff[0] + kB);
            LDSM4(bL + 4, stBL + bOff[1] + kB);
            // 3 passes from the same fragments: AhBh, AlBh, AhBl
#pragma unroll
            for (int mt = 0; mt < 2; mt++)
#pragma unroll
                for (int nt = 0; nt < 4; nt++) {
                    mma16816(acc[mt][nt], aH + mt * 4, bH + nt * 2);
                    mma16816(acc[mt][nt], aL + mt * 4, bH + nt * 2);
                    mma16816(acc[mt][nt], aH + mt * 4, bL + nt * 2);
                }
        }

        // relation boundary: bias + PReLU -> run, reset acc
        if ((c & 7) == 7) {
            const int r = c >> 3;
#pragma unroll
            for (int nt = 0; nt < 4; nt++) {
                const float b0 = biasS[r * TN + wn + nt * 8 + t2];
                const float b1 = biasS[r * TN + wn + nt * 8 + t2 + 1];
#pragma unroll
                for (int mt = 0; mt < 2; mt++) {
                    float h;
                    h = acc[mt][nt][0] + b0; h = (h >= 0.f) ? h : alpha * h; run[mt][nt][0] += h;
                    h = acc[mt][nt][1] + b1; h = (h >= 0.f) ? h : alpha * h; run[mt][nt][1] += h;
                    h = acc[mt][nt][2] + b0; h = (h >= 0.f) ? h : alpha * h; run[mt][nt][2] += h;
                    h = acc[mt][nt][3] + b1; h = (h >= 0.f) ? h : alpha * h; run[mt][nt][3] += h;
                    acc[mt][nt][0] = 0.f; acc[mt][nt][1] = 0.f;
                    acc[mt][nt][2] = 0.f; acc[mt][nt][3] = 0.f;
                }
            }
        }
    }

    // mean over relations, store. c-frag rows: g / g+8; cols: t2, t2+1.
#pragma unroll
    for (int mt = 0; mt < 2; mt++) {
#pragma unroll
        for (int nt = 0; nt < 4; nt++) {
            const int row0 = bm0 + wm + mt * 16 + g;
            const int col  = bn0 + wn + nt * 8 + t2;
            float2 v0 = make_float2(run[mt][nt][0] * 0.25f, run[mt][nt][1] * 0.25f);
            float2 v1 = make_float2(run[mt][nt][2] * 0.25f, run[mt][nt][3] * 0.25f);
            *(float2*)(out + (size_t)row0 * OUT_FT + col)       = v0;
            *(float2*)(out + (size_t)(row0 + 8) * OUT_FT + col) = v1;
        }
    }
}

// ---------------------------------------------------------------------------
// Launch. Inputs (metadata order): features, neighbor_idx, W, b, prelu_a,
// node_list, k. node_list/k are unused by the reference math.
// ---------------------------------------------------------------------------
extern "C" void kernel_launch(void* const* d_in, const int* in_sizes, int n_in,
                              void* d_out, int out_size)
{
    const float* features = (const float*)d_in[0];
    const int*   nidx     = (const int*)d_in[1];
    const float* W        = (const float*)d_in[2];
    const float* bias     = (const float*)d_in[3];
    const float* prelu_a  = (const float*)d_in[4];
    float* out = (float*)d_out;

    // Idempotent attribute set (not a stream op; graph-capture safe).
    cudaFuncSetAttribute(rgcn_mma_kernel,
                         cudaFuncAttributeMaxDynamicSharedMemorySize, SMEM_DYN);

    // Fused gather (8192 blocks) + W prep (1024 blocks)
    prep_kernel<<<8192 + NB_REL * OUT_FT, 256>>>(features, nidx, W);

    dim3 grid(BATCH / TM, OUT_FT / TN);   // (64, 4) = 256 CTAs
    rgcn_mma_kernel<<<grid, 256, SMEM_DYN>>>(bias, prelu_a, out);
}